// round 10
// baseline (speedup 1.0000x reference)
#include <cuda_runtime.h>
#include <math.h>
#include <stdint.h>

typedef unsigned long long ull;

#define BATCH 64
#define SEQ   2048
#define IN_F  256
#define HID   512
#define RANKS 8     // CTAs per cluster; each owns 64 columns of W_hh
#define BPC   4     // batch rows per cluster (2 per half)

// half-buffer geometry: 8 regions, each 32 entries x 16B = 512B payload,
// padded to 528B stride so region r starts at bank offset 4r (conflict-free).
#define REG_PAY  512
#define REG_STR  528
#define BUF_STR  (RANKS * REG_STR)   // 4224 per buffer
#define EXCH_TX  (7 * REG_PAY)       // 3584 incoming bytes per half per step

// ---------------------------------------------------------------------------
// Packed f32x2 helpers
// ---------------------------------------------------------------------------
__device__ __forceinline__ ull ffma2(ull a, ull b, ull c) {
    ull d;
    asm("fma.rn.f32x2 %0, %1, %2, %3;" : "=l"(d) : "l"(a), "l"(b), "l"(c));
    return d;
}
__device__ __forceinline__ ull addx2(ull a, ull b) {
    ull d;
    asm("add.rn.f32x2 %0, %1, %2;" : "=l"(d) : "l"(a), "l"(b));
    return d;
}
__device__ __forceinline__ ull dup2(float x) {
    ull d;
    asm("mov.b64 %0, {%1, %1};" : "=l"(d) : "f"(x));
    return d;
}
__device__ __forceinline__ ull pack2(float lo, float hi) {
    ull d;
    asm("mov.b64 %0, {%1, %2};" : "=l"(d) : "f"(lo), "f"(hi));
    return d;
}
__device__ __forceinline__ float f2lo(ull v) {
    return __int_as_float((int)(unsigned int)(v & 0xffffffffULL));
}
__device__ __forceinline__ float f2hi(ull v) {
    return __int_as_float((int)(unsigned int)(v >> 32));
}

// ---------------------------------------------------------------------------
// mbarrier / cluster primitives
// ---------------------------------------------------------------------------
__device__ __forceinline__ void mbar_init(uint32_t mbar, uint32_t cnt) {
    asm volatile("mbarrier.init.shared.b64 [%0], %1;" :: "r"(mbar), "r"(cnt) : "memory");
}
__device__ __forceinline__ void mbar_expect_tx(uint32_t mbar, uint32_t bytes) {
    asm volatile("mbarrier.arrive.expect_tx.shared.b64 _, [%0], %1;"
                 :: "r"(mbar), "r"(bytes) : "memory");
}
__device__ __forceinline__ void mbar_wait(uint32_t mbar, uint32_t parity) {
    asm volatile(
        "{\n\t"
        ".reg .pred P;\n\t"
        "WL_%=:\n\t"
        "mbarrier.try_wait.parity.acquire.cta.shared::cta.b64 P, [%0], %1;\n\t"
        "@P bra.uni WD_%=;\n\t"
        "bra.uni WL_%=;\n\t"
        "WD_%=:\n\t"
        "}"
        :: "r"(mbar), "r"(parity) : "memory");
}
// bulk copy: our smem region -> same offset in cluster rank r, signal r's mbar
__device__ __forceinline__ void cluster_bulk_copy(uint32_t local_addr, uint32_t bytes,
                                                  uint32_t local_mbar, int r) {
    uint32_t rdst, rmb;
    asm volatile("mapa.shared::cluster.u32 %0, %1, %2;" : "=r"(rdst) : "r"(local_addr), "r"(r));
    asm volatile("mapa.shared::cluster.u32 %0, %1, %2;" : "=r"(rmb) : "r"(local_mbar), "r"(r));
    asm volatile(
        "cp.async.bulk.shared::cluster.shared::cta.mbarrier::complete_tx::bytes "
        "[%0], [%1], %2, [%3];"
        :: "r"(rdst), "r"(local_addr), "r"(bytes), "r"(rmb) : "memory");
}
__device__ __forceinline__ void cluster_sync_() {
    asm volatile("barrier.cluster.arrive.aligned;" ::: "memory");
    asm volatile("barrier.cluster.wait.aligned;" ::: "memory");
}

// ---------------------------------------------------------------------------
// Kernel 1: x_proj GEMM  out[m][n] = sum_k X[m][k]*Wih[n][k] + bih[n] + bhh[n]
// ---------------------------------------------------------------------------
#define BM 128
#define BN 64
#define BK 32
#define ASP 130

__global__ __launch_bounds__(256) void xproj_kernel(
    const float* __restrict__ X, const float* __restrict__ Wih,
    const float* __restrict__ bih, const float* __restrict__ bhh,
    float* __restrict__ out)
{
    __shared__ float As[BK][ASP];
    __shared__ float Ws[BK][BN];

    const int tid = threadIdx.x;
    const int m0 = blockIdx.x * BM;
    const int n0 = blockIdx.y * BN;
    const int tx = tid & 15;
    const int ty = tid >> 4;

    ull acc[4][4];
#pragma unroll
    for (int r = 0; r < 4; r++)
#pragma unroll
        for (int c = 0; c < 4; c++) acc[r][c] = 0ULL;

    for (int k0 = 0; k0 < IN_F; k0 += BK) {
#pragma unroll
        for (int i = 0; i < 4; i++) {
            int idx = tid + i * 256;
            int m = idx >> 3;
            int k4 = idx & 7;
            float4 v = *(const float4*)(X + (size_t)(m0 + m) * IN_F + k0 + k4 * 4);
            As[k4 * 4 + 0][m] = v.x;
            As[k4 * 4 + 1][m] = v.y;
            As[k4 * 4 + 2][m] = v.z;
            As[k4 * 4 + 3][m] = v.w;
        }
#pragma unroll
        for (int i = 0; i < 2; i++) {
            int idx = tid + i * 256;
            int n = idx >> 3;
            int k4 = idx & 7;
            float4 v = *(const float4*)(Wih + (size_t)(n0 + n) * IN_F + k0 + k4 * 4);
            Ws[k4 * 4 + 0][n] = v.x;
            Ws[k4 * 4 + 1][n] = v.y;
            Ws[k4 * 4 + 2][n] = v.z;
            Ws[k4 * 4 + 3][n] = v.w;
        }
        __syncthreads();

#pragma unroll
        for (int k = 0; k < BK; k++) {
            ull ap[4];
#pragma unroll
            for (int r = 0; r < 4; r++)
                ap[r] = *(const ull*)&As[k][ty * 8 + 2 * r];
            float4 wv = *(const float4*)&Ws[k][tx * 4];
            ull wd0 = dup2(wv.x), wd1 = dup2(wv.y);
            ull wd2 = dup2(wv.z), wd3 = dup2(wv.w);
#pragma unroll
            for (int r = 0; r < 4; r++) {
                acc[r][0] = ffma2(ap[r], wd0, acc[r][0]);
                acc[r][1] = ffma2(ap[r], wd1, acc[r][1]);
                acc[r][2] = ffma2(ap[r], wd2, acc[r][2]);
                acc[r][3] = ffma2(ap[r], wd3, acc[r][3]);
            }
        }
        __syncthreads();
    }

    float bsum[4];
#pragma unroll
    for (int c = 0; c < 4; c++) {
        int n = n0 + tx * 4 + c;
        bsum[c] = bih[n] + bhh[n];
    }
#pragma unroll
    for (int r = 0; r < 4; r++) {
        size_t mlo = (size_t)(m0 + ty * 8 + 2 * r);
        float4 lo4, hi4;
        lo4.x = f2lo(acc[r][0]) + bsum[0]; lo4.y = f2lo(acc[r][1]) + bsum[1];
        lo4.z = f2lo(acc[r][2]) + bsum[2]; lo4.w = f2lo(acc[r][3]) + bsum[3];
        hi4.x = f2hi(acc[r][0]) + bsum[0]; hi4.y = f2hi(acc[r][1]) + bsum[1];
        hi4.z = f2hi(acc[r][2]) + bsum[2]; hi4.w = f2hi(acc[r][3]) + bsum[3];
        *(float4*)(out + mlo * HID + n0 + tx * 4)       = lo4;
        *(float4*)(out + (mlo + 1) * HID + n0 + tx * 4) = hi4;
    }
}

// ---------------------------------------------------------------------------
// Kernel 2: cluster scan. R6 protocol (single mbar per buffer per half) +
// bank-conflict-free layout + k-pair FFMA2 (no dup movs) + batch-half
// pipelining (exchange of half X overlaps compute of half Y).
//
// 16 clusters x 8 CTAs; CTA rank owns columns [64r, 64r+64). 512 threads:
// col = tid>>3 (output column), kq = tid&7 (k-chunk of 64 = region kq).
//
// h layout per half (rows rA=(b0,b1) / rB=(b2,b3)):
//   2 buffers x 8 regions; region stride 528B (bank-skewed), payload 512B =
//   32 entries x 16B. Entry c of region r, for k0 = r*64+2c:
//     [0:8)  = (h_rowlo[k0], h_rowlo[k0+1])   [8:16) = (h_rowhi[k0], ...)
//   Thread (col,kq) reads region kq entries 0..31: LDS.128, lanes with equal
//   kq broadcast; across kq banks 4kq+4c -> conflict-free.
//
// W regs: wl[j] = (Whh[gcol][kq*64+2j], Whh[gcol][kq*64+2j+1]) packed ull.
// FFMA2 accumulates even-k in .lo, odd-k in .hi; one FADD folds them.
// Butterfly over the 8 kq lanes on pack2(s_rowlo, s_rowhi); lanes kq=0/1
// output rows lo/hi.
//
// Per half per step: wait mbar[p] -> compute -> reduce -> tanh -> writer
// lanes (kq<2, col even) STS entry of buf[1-p] -> arm mbar[1-p] ->
// __syncthreads -> warps (1..7 | 9..15) each bulk-copy our 512B region to
// one peer, signaling the peer's mbar[1-p] via complete_tx.
// ---------------------------------------------------------------------------
__global__ void __cluster_dims__(RANKS, 1, 1) __launch_bounds__(512, 1)
scan_kernel(const float* __restrict__ h0, const float* __restrict__ Whh,
            float* __restrict__ out)
{
    __shared__ __align__(16) char hA[2 * BUF_STR];
    __shared__ __align__(16) char hB[2 * BUF_STR];
    __shared__ __align__(8) ull mbars[4];      // A0 A1 B0 B1

    const int tid  = threadIdx.x;
    const int kq   = tid & 7;
    const int col  = tid >> 3;                 // 0..63
    const int wid  = tid >> 5;                 // warp 0..15
    const int rank = blockIdx.x & (RANKS - 1);
    const int cid  = blockIdx.x >> 3;
    const int b0   = cid * BPC;
    const int gcol = rank * 64 + col;

    // ---- W slice as packed k-pairs (contiguous, vector loads)
    ull wl[32];
    {
        const ull* wp = (const ull*)(Whh + (size_t)gcol * HID + kq * 64);
#pragma unroll
        for (int j = 0; j < 32; j++) wl[j] = wp[j];
    }

    const uint32_t hpA = (uint32_t)__cvta_generic_to_shared(hA);
    const uint32_t hpB = (uint32_t)__cvta_generic_to_shared(hB);
    const uint32_t mbb = (uint32_t)__cvta_generic_to_shared(mbars);

    if (tid < 4) mbar_init(mbb + tid * 8, 1);

    // ---- preload h0 into buffer 0 of both halves (k = tid)
    {
        const int k = tid;
        const int r = k >> 6;
        const int eo = r * REG_STR + ((k & 63) >> 1) * 16 + (k & 1) * 4;
        *(float*)(hA + eo)     = h0[(size_t)(b0 + 0) * HID + k];
        *(float*)(hA + eo + 8) = h0[(size_t)(b0 + 1) * HID + k];
        *(float*)(hB + eo)     = h0[(size_t)(b0 + 2) * HID + k];
        *(float*)(hB + eo + 8) = h0[(size_t)(b0 + 3) * HID + k];
    }
    __syncthreads();
    cluster_sync_();            // mbar inits + buffer0 visible cluster-wide

    // output lanes: kq 0/1 -> row lo/hi of each half
    const bool outl = (kq < 2);
    const int  okq  = outl ? kq : 0;
    const size_t oA = ((size_t)(b0 + okq) * SEQ) * HID + gcol;
    const size_t oB = ((size_t)(b0 + 2 + okq) * SEQ) * HID + gcol;
    float xA = 0.0f, xB = 0.0f;
    if (outl) { xA = out[oA]; xB = out[oB]; }

    for (int t = 0; t < SEQ; t++) {
        const int p = t & 1;
        const uint32_t par = (uint32_t)(((t - 1) >> 1) & 1);
        const bool guard = (t < SEQ - 1);
        const uint32_t boff  = (uint32_t)(p * BUF_STR);
        const uint32_t bnoff = (uint32_t)((1 - p) * BUF_STR);

        // ================= HALF A (rows b0, b1) =================
        if (t) mbar_wait(mbb + (uint32_t)(p * 8), par);
        float vA;
        {
            const ulonglong2* base =
                (const ulonglong2*)(hA + boff + kq * REG_STR);
            ull a0 = 0, a1 = 0;
#pragma unroll
            for (int j = 0; j < 32; j++) {
                ulonglong2 e = base[j];
                a0 = ffma2(wl[j], e.x, a0);
                a1 = ffma2(wl[j], e.y, a1);
            }
            ull x = pack2(f2lo(a0) + f2hi(a0), f2lo(a1) + f2hi(a1));
            x = addx2(x, __shfl_xor_sync(0xffffffffu, x, 1));
            x = addx2(x, __shfl_xor_sync(0xffffffffu, x, 2));
            x = addx2(x, __shfl_xor_sync(0xffffffffu, x, 4));
            vA = 0.0f;
            if (outl) {
                float sv = (kq & 1) ? f2hi(x) : f2lo(x);
                vA = tanhf(sv + xA);
            }
        }
        {
            // gather neighbors for the 16B entry write
            float n1 = __shfl_down_sync(0xffffffffu, vA, 1);   // row hi, same col
            float n8 = __shfl_down_sync(0xffffffffu, vA, 8);   // row lo, col+1
            float n9 = __shfl_down_sync(0xffffffffu, vA, 9);   // row hi, col+1
            if (guard && kq == 0 && !(col & 1)) {
                ulonglong2 e;
                e.x = pack2(vA, n8);   // row lo: (k0, k0+1)
                e.y = pack2(n1, n9);   // row hi: (k0, k0+1)
                *(ulonglong2*)(hA + bnoff + rank * REG_STR + (col >> 1) * 16) = e;
            }
        }
        if (guard) {
            if (tid == 0) mbar_expect_tx(mbb + (uint32_t)((1 - p) * 8), EXCH_TX);
            __syncthreads();
            if (wid >= 1 && wid <= 7 && (tid & 31) == 0) {
                asm volatile("fence.proxy.async.shared::cta;" ::: "memory");
                cluster_bulk_copy(hpA + bnoff + rank * REG_STR, REG_PAY,
                                  mbb + (uint32_t)((1 - p) * 8),
                                  (rank - wid) & (RANKS - 1));
            }
        }

        // ================= HALF B (rows b2, b3) =================
        if (t) mbar_wait(mbb + (uint32_t)(16 + p * 8), par);
        float vB;
        {
            const ulonglong2* base =
                (const ulonglong2*)(hB + boff + kq * REG_STR);
            ull a0 = 0, a1 = 0;
#pragma unroll
            for (int j = 0; j < 32; j++) {
                ulonglong2 e = base[j];
                a0 = ffma2(wl[j], e.x, a0);
                a1 = ffma2(wl[j], e.y, a1);
            }
            ull x = pack2(f2lo(a0) + f2hi(a0), f2lo(a1) + f2hi(a1));
            x = addx2(x, __shfl_xor_sync(0xffffffffu, x, 1));
            x = addx2(x, __shfl_xor_sync(0xffffffffu, x, 2));
            x = addx2(x, __shfl_xor_sync(0xffffffffu, x, 4));
            vB = 0.0f;
            if (outl) {
                float sv = (kq & 1) ? f2hi(x) : f2lo(x);
                vB = tanhf(sv + xB);
            }
        }
        {
            float n1 = __shfl_down_sync(0xffffffffu, vB, 1);
            float n8 = __shfl_down_sync(0xffffffffu, vB, 8);
            float n9 = __shfl_down_sync(0xffffffffu, vB, 9);
            if (guard && kq == 0 && !(col & 1)) {
                ulonglong2 e;
                e.x = pack2(vB, n8);
                e.y = pack2(n1, n9);
                *(ulonglong2*)(hB + bnoff + rank * REG_STR + (col >> 1) * 16) = e;
            }
        }
        if (guard) {
            if (tid == 256) mbar_expect_tx(mbb + (uint32_t)(16 + (1 - p) * 8), EXCH_TX);
            __syncthreads();
            if (wid >= 9 && (tid & 31) == 0) {
                asm volatile("fence.proxy.async.shared::cta;" ::: "memory");
                cluster_bulk_copy(hpB + bnoff + rank * REG_STR, REG_PAY,
                                  mbb + (uint32_t)(16 + (1 - p) * 8),
                                  (rank - (wid - 8)) & (RANKS - 1));
            }
        }

        // ---- outputs + next-step xp prefetch (off the exchange path)
        if (outl) {
            out[oA + (size_t)t * HID] = vA;
            out[oB + (size_t)t * HID] = vB;
            if (guard) {
                xA = out[oA + (size_t)(t + 1) * HID];
                xB = out[oB + (size_t)(t + 1) * HID];
            }
        }
    }

    cluster_sync_();
}

// ---------------------------------------------------------------------------
// Launch
// ---------------------------------------------------------------------------
extern "C" void kernel_launch(void* const* d_in, const int* in_sizes, int n_in,
                              void* d_out, int out_size) {
    const float* x_in = (const float*)d_in[0];
    const float* h0   = (const float*)d_in[1];
    const float* W_ih = (const float*)d_in[2];
    const float* W_hh = (const float*)d_in[3];
    const float* b_ih = (const float*)d_in[4];
    const float* b_hh = (const float*)d_in[5];
    float* out = (float*)d_out;

    dim3 gg((BATCH * SEQ) / BM, HID / BN);
    xproj_kernel<<<gg, 256>>>(x_in, W_ih, b_ih, b_hh, out);

    scan_kernel<<<(BATCH / BPC) * RANKS, 512>>>(h0, W_hh, out);
}